// round 14
// baseline (speedup 1.0000x reference)
#include <cuda_runtime.h>
#include <cuda_bf16.h>
#include <cuda_fp16.h>

#define BB 8
#define SS 1024
#define HH 8
#define DD 128
#define HD 1024

// ---- scratch planes ----
__device__ __half g_Xq[(size_t)BB*SS*128];
__device__ __half g_Xk[(size_t)BB*SS*128];
__device__ __half g_Xv[(size_t)BB*SS*128];
__device__ __half g_Wq[HD*128], g_Wk[HD*128], g_Wv[HD*128];
__device__ __half g_Wc[128*HD];
__device__ signed char g_Qi[(size_t)BB*HH*SS*DD];   // int8, scale 96
__device__ signed char g_Ki[(size_t)BB*HH*SS*DD];   // int8, scale 96
__device__ __half g_V[(size_t)BB*HH*SS*DD];
__device__ __half g_O[(size_t)BB*SS*HD];

#define QSCALE 96.0f
// softmax scale / (96*96)
#define SFAC 9.590852827205e-6f

// ---- helpers ----
__device__ __forceinline__ void mma16816h(float* c, const unsigned* a, const unsigned* b) {
    asm volatile(
        "mma.sync.aligned.m16n8k16.row.col.f32.f16.f16.f32 "
        "{%0,%1,%2,%3}, {%4,%5,%6,%7}, {%8,%9}, {%0,%1,%2,%3};\n"
        : "+f"(c[0]), "+f"(c[1]), "+f"(c[2]), "+f"(c[3])
        : "r"(a[0]), "r"(a[1]), "r"(a[2]), "r"(a[3]), "r"(b[0]), "r"(b[1]));
}
__device__ __forceinline__ void mma16832i(int* c, const unsigned* a, const unsigned* b) {
    asm volatile(
        "mma.sync.aligned.m16n8k32.row.col.s32.s8.s8.s32 "
        "{%0,%1,%2,%3}, {%4,%5,%6,%7}, {%8,%9}, {%0,%1,%2,%3};\n"
        : "+r"(c[0]), "+r"(c[1]), "+r"(c[2]), "+r"(c[3])
        : "r"(a[0]), "r"(a[1]), "r"(a[2]), "r"(a[3]), "r"(b[0]), "r"(b[1]));
}
__device__ __forceinline__ void ldsm4(unsigned* r, unsigned addr) {
    asm volatile("ldmatrix.sync.aligned.m8n8.x4.shared.b16 {%0,%1,%2,%3}, [%4];"
        : "=r"(r[0]), "=r"(r[1]), "=r"(r[2]), "=r"(r[3]) : "r"(addr));
}
__device__ __forceinline__ void ldsm4t(unsigned* r, unsigned addr) {
    asm volatile("ldmatrix.sync.aligned.m8n8.x4.trans.shared.b16 {%0,%1,%2,%3}, [%4];"
        : "=r"(r[0]), "=r"(r[1]), "=r"(r[2]), "=r"(r[3]) : "r"(addr));
}
__device__ __forceinline__ unsigned cvth2(float hi, float lo) {
    unsigned r;
    asm("cvt.rn.f16x2.f32 %0, %1, %2;" : "=r"(r) : "f"(hi), "f"(lo));
    return r;
}
__device__ __forceinline__ unsigned short packq2(float x0, float x1) {
    int v0 = max(-127, min(127, __float2int_rn(x0 * QSCALE)));
    int v1 = max(-127, min(127, __float2int_rn(x1 * QSCALE)));
    return (unsigned short)((v0 & 0xff) | ((v1 & 0xff) << 8));
}
__device__ __forceinline__ void cpa(unsigned dst, const void* src) {
    asm volatile("cp.async.cg.shared.global [%0], [%1], 16;" :: "r"(dst), "l"(src));
}
__device__ __forceinline__ void cpa_commit() { asm volatile("cp.async.commit_group;"); }
template<int N> __device__ __forceinline__ void cpa_wait() {
    asm volatile("cp.async.wait_group %0;" :: "n"(N));
}

// ---------------------------------------------------------------------------
// Convert fp32 operands to single fp16 planes (one-time, memory-bound).
// ---------------------------------------------------------------------------
__global__ __launch_bounds__(256) void convert_kernel(
    const float* __restrict__ q, const float* __restrict__ k, const float* __restrict__ v,
    const float* __restrict__ Wq, const float* __restrict__ Wk, const float* __restrict__ Wv,
    const float* __restrict__ Wc)
{
    const float* src; __half* dh; int n4;
    switch (blockIdx.y) {
        case 0: src = q;  dh = g_Xq; n4 = BB*SS*128/4; break;
        case 1: src = k;  dh = g_Xk; n4 = BB*SS*128/4; break;
        case 2: src = v;  dh = g_Xv; n4 = BB*SS*128/4; break;
        case 3: src = Wq; dh = g_Wq; n4 = HD*128/4; break;
        case 4: src = Wk; dh = g_Wk; n4 = HD*128/4; break;
        case 5: src = Wv; dh = g_Wv; n4 = HD*128/4; break;
        default: src = Wc; dh = g_Wc; n4 = 128*HD/4; break;
    }
    for (int i = blockIdx.x*256 + threadIdx.x; i < n4; i += gridDim.x*256) {
        float4 f = ((const float4*)src)[i];
        ((uint2*)dh)[i] = make_uint2(cvth2(f.y, f.x), cvth2(f.w, f.z));
    }
}

// ---------------------------------------------------------------------------
// Fused QKV projection (validated r11 core). Epilogue: Q/K int8, V fp16.
// ---------------------------------------------------------------------------
__global__ __launch_bounds__(256) void qkv_proj_kernel()
{
    extern __shared__ char smq[];
    const unsigned su = (unsigned)__cvta_generic_to_shared(smq);

    const uint4 *Xp, *Wp;
    if (blockIdx.z == 0)      { Xp=(const uint4*)g_Xq; Wp=(const uint4*)g_Wq; }
    else if (blockIdx.z == 1) { Xp=(const uint4*)g_Xk; Wp=(const uint4*)g_Wk; }
    else                      { Xp=(const uint4*)g_Xv; Wp=(const uint4*)g_Wv; }

    const int m0 = blockIdx.y * 64;
    const int h  = blockIdx.x;
    const int tid = threadIdx.x;
    const int lane = tid & 31;
    const int wid  = tid >> 5;
    const int band = wid & 3, side = wid >> 2;
    const int g    = lane >> 2, tig = lane & 3;

    #pragma unroll
    for (int t = 0; t < 4; t++) {
        int idx = tid + 256*t;
        int r = idx >> 4, c = idx & 15;
        cpa(su + (unsigned)(r*16 + (c^(r&7)))*16, Xp + (size_t)(m0+r)*16 + c);
    }
    #pragma unroll
    for (int t = 0; t < 8; t++) {
        int idx = tid + 256*t;
        int r = idx >> 4, c = idx & 15;
        cpa(su + 16384u + (unsigned)(r*16 + (c^(r&7)))*16, Wp + (size_t)(h*128+r)*16 + c);
    }
    cpa_commit();
    cpa_wait<0>();
    __syncthreads();

    float acc[8][4];
    #pragma unroll
    for (int nt = 0; nt < 8; nt++)
        #pragma unroll
        for (int c = 0; c < 4; c++) acc[nt][c] = 0.f;

    const int arow = band*16 + (lane & 7) + ((lane >> 3) & 1)*8;
    const int abit = lane >> 4;
    const int kb   = (lane & 7) + ((lane >> 4) & 1)*8;
    const int kbit = (lane >> 3) & 1;

    #pragma unroll
    for (int ks = 0; ks < 8; ks++) {
        unsigned a_h[4];
        unsigned aaddr = su + (unsigned)(arow*16 + ((2*ks+abit) ^ (arow&7)))*16;
        ldsm4(a_h, aaddr);
        unsigned bh_[4][4];
        #pragma unroll
        for (int np = 0; np < 4; np++) {
            int brow = side*64 + np*16 + kb;
            unsigned baddr = su + 16384u + (unsigned)(brow*16 + ((2*ks+kbit) ^ (brow&7)))*16;
            ldsm4(bh_[np], baddr);
        }
        #pragma unroll
        for (int np = 0; np < 4; np++) {
            mma16816h(acc[2*np],   a_h, bh_[np]);
            mma16816h(acc[2*np+1], a_h, bh_[np]+2);
        }
    }

    #pragma unroll
    for (int nt = 0; nt < 8; nt++) {
        int col = side*64 + nt*8 + 2*tig;
        int ma = m0 + band*16 + g;
        int mb2 = ma + 8;
        size_t offa = (((size_t)((ma  >> 10)*HH + h))*SS + (ma  & 1023))*DD + col;
        size_t offb = (((size_t)((mb2 >> 10)*HH + h))*SS + (mb2 & 1023))*DD + col;
        if (blockIdx.z == 2) {
            *(unsigned*)(g_V + offa) = cvth2(acc[nt][1], acc[nt][0]);
            *(unsigned*)(g_V + offb) = cvth2(acc[nt][3], acc[nt][2]);
        } else {
            signed char* Oi = (blockIdx.z == 0) ? g_Qi : g_Ki;
            *(unsigned short*)(Oi + offa) = packq2(acc[nt][0], acc[nt][1]);
            *(unsigned short*)(Oi + offb) = packq2(acc[nt][2], acc[nt][3]);
        }
    }
}

// ---------------------------------------------------------------------------
// Flash attention: QK int8 (m16n8k32.s8), PV fp16. 256 thr / 8 warps,
// cp.async double-buffered K/V, 2 CTAs/SM.
// smem: msk 0 (4KB), Qi 4096 (16KB), KV0 20480 (24KB: Ki+0, V+8192),
//       KV1 45056 (24KB). Total 68KB.
// int8 tiles: 128B row pitch, 8 swizzle chunks (c ^ (r&7), c<8).
// ---------------------------------------------------------------------------
__global__ __launch_bounds__(256, 2) void attn_kernel(const float* __restrict__ mask)
{
    extern __shared__ char sm[];
    float* msk_s = (float*)sm;
    const unsigned smem_u = (unsigned)__cvta_generic_to_shared(sm);
    const unsigned offQ = 4096u, KV0 = 20480u, KV1 = 45056u;

    const int tid  = threadIdx.x;
    const int lane = tid & 31;
    const int wid  = tid >> 5;
    const int wq0  = wid * 16;
    const int g    = lane >> 2;
    const int tig  = lane & 3;

    const int bh = blockIdx.y;
    const int b_ = bh >> 3, h = bh & 7;
    const int q0 = blockIdx.x * 128;

    const uint4* qi4 = (const uint4*)(g_Qi + ((size_t)bh*SS + q0)*DD);
    const uint4* ki4 = (const uint4*)(g_Ki + (size_t)bh*SS*DD);
    const uint4* vh4 = (const uint4*)(g_V  + (size_t)bh*SS*DD);
    const float* mb = mask + b_*SS;

    // mask (1024 floats) + Q int8 plane (128 rows x 8 chunks)
    *(float4*)&msk_s[tid*4] = ((const float4*)mb)[tid];
    #pragma unroll
    for (int t = 0; t < 4; t++) {
        int idx = tid + 256*t;
        int r = idx >> 3, c = idx & 7;
        unsigned phys = (unsigned)(r*8 + (c ^ (r&7)))*16;
        *(uint4*)(sm + 4096 + phys) = qi4[idx];
    }
    // prefetch KV block 0: K int8 (64x8 chunks), V fp16 (64x16 chunks)
    {
        #pragma unroll
        for (int t = 0; t < 2; t++) {
            int idx = tid + 256*t;
            int r = idx >> 3, c = idx & 7;
            cpa(smem_u + KV0 + (unsigned)(r*8 + (c^(r&7)))*16, ki4 + idx);
        }
        #pragma unroll
        for (int t = 0; t < 4; t++) {
            int idx = tid + 256*t;
            int r = idx >> 4, c = idx & 15;
            cpa(smem_u + KV0 + 8192u + (unsigned)(r*16 + (c^(r&7)))*16, vh4 + idx);
        }
        cpa_commit();
    }

    float o[16][4];
    #pragma unroll
    for (int nt = 0; nt < 16; nt++)
        #pragma unroll
        for (int c = 0; c < 4; c++) o[nt][c] = 0.f;

    float m0s = -3.0e38f, m1s = -3.0e38f, l0s = 0.f, l1s = 0.f;

    const int arow = wq0 + (lane & 7) + ((lane >> 3) & 1)*8;
    const int abit = lane >> 4;
    const int kbr  = (lane & 7) + ((lane >> 4) & 1)*8;
    const int kbit = (lane >> 3) & 1;
    const int vr   = (lane & 7) + ((lane >> 3) & 1)*8;
    const int vbit = (lane >> 4) & 1;

    for (int it = 0; it < 16; it++) {
        const int j0 = it*64;
        const unsigned kvcur = (it & 1) ? KV1 : KV0;
        if (it < 15) {
            const unsigned kvnxt = (it & 1) ? KV0 : KV1;
            #pragma unroll
            for (int t = 0; t < 2; t++) {
                int idx = tid + 256*t;
                int r = idx >> 3, c = idx & 7;
                cpa(smem_u + kvnxt + (unsigned)(r*8 + (c^(r&7)))*16,
                    ki4 + (j0 + 64)*8 + idx);
            }
            #pragma unroll
            for (int t = 0; t < 4; t++) {
                int idx = tid + 256*t;
                int r = idx >> 4, c = idx & 15;
                cpa(smem_u + kvnxt + 8192u + (unsigned)(r*16 + (c^(r&7)))*16,
                    vh4 + (j0 + 64 + r)*16 + c);
            }
            cpa_commit();
            cpa_wait<1>();
        } else {
            cpa_wait<0>();
        }
        __syncthreads();

        // ---- S = Q K^T (int8, m16n8k32) ----
        int isacc[8][4];
        #pragma unroll
        for (int nt = 0; nt < 8; nt++)
            #pragma unroll
            for (int c = 0; c < 4; c++) isacc[nt][c] = 0;

        #pragma unroll
        for (int ks = 0; ks < 4; ks++) {
            unsigned a_h[4];
            unsigned aaddr = smem_u + offQ + (unsigned)(arow*8 + ((2*ks+abit) ^ (arow&7)))*16;
            ldsm4(a_h, aaddr);
            unsigned bi_[4][4];
            #pragma unroll
            for (int np = 0; np < 4; np++) {
                int brow = np*16 + kbr;
                unsigned baddr = smem_u + kvcur + (unsigned)(brow*8 + ((2*ks+kbit) ^ (brow&7)))*16;
                ldsm4(bi_[np], baddr);
            }
            #pragma unroll
            for (int np = 0; np < 4; np++) {
                mma16832i(isacc[2*np],   a_h, bi_[np]);
                mma16832i(isacc[2*np+1], a_h, bi_[np]+2);
            }
        }

        // dequant + mask
        float sacc[8][4];
        float mx0 = -3.0e38f, mx1 = -3.0e38f;
        #pragma unroll
        for (int nt = 0; nt < 8; nt++) {
            float2 mk = *(float2*)&msk_s[j0 + nt*8 + 2*tig];
            sacc[nt][0] = (float)isacc[nt][0]*SFAC + mk.x;
            sacc[nt][1] = (float)isacc[nt][1]*SFAC + mk.y;
            sacc[nt][2] = (float)isacc[nt][2]*SFAC + mk.x;
            sacc[nt][3] = (float)isacc[nt][3]*SFAC + mk.y;
            mx0 = fmaxf(mx0, fmaxf(sacc[nt][0], sacc[nt][1]));
            mx1 = fmaxf(mx1, fmaxf(sacc[nt][2], sacc[nt][3]));
        }
        #pragma unroll
        for (int mskb = 1; mskb <= 2; mskb <<= 1) {
            mx0 = fmaxf(mx0, __shfl_xor_sync(0xffffffffu, mx0, mskb));
            mx1 = fmaxf(mx1, __shfl_xor_sync(0xffffffffu, mx1, mskb));
        }
        float mn0 = fmaxf(m0s, mx0), mn1 = fmaxf(m1s, mx1);
        float al0 = __expf(m0s - mn0), al1 = __expf(m1s - mn1);
        m0s = mn0; m1s = mn1;

        float sum0 = 0.f, sum1 = 0.f;
        #pragma unroll
        for (int nt = 0; nt < 8; nt++) {
            float p0 = __expf(sacc[nt][0] - mn0);
            float p1 = __expf(sacc[nt][1] - mn0);
            float p2 = __expf(sacc[nt][2] - mn1);
            float p3 = __expf(sacc[nt][3] - mn1);
            sacc[nt][0] = p0; sacc[nt][1] = p1; sacc[nt][2] = p2; sacc[nt][3] = p3;
            sum0 += p0 + p1; sum1 += p2 + p3;
        }
        #pragma unroll
        for (int mskb = 1; mskb <= 2; mskb <<= 1) {
            sum0 += __shfl_xor_sync(0xffffffffu, sum0, mskb);
            sum1 += __shfl_xor_sync(0xffffffffu, sum1, mskb);
        }
        l0s = l0s*al0 + sum0;
        l1s = l1s*al1 + sum1;

        #pragma unroll
        for (int nt = 0; nt < 16; nt++) {
            o[nt][0] *= al0; o[nt][1] *= al0;
            o[nt][2] *= al1; o[nt][3] *= al1;
        }

        // ---- O += P V (fp16, validated) ----
        #pragma unroll
        for (int kk = 0; kk < 4; kk++) {
            unsigned pah[4];
            #pragma unroll
            for (int half = 0; half < 2; half++) {
                int nt = 2*kk + half;
                pah[2*half]   = cvth2(sacc[nt][1], sacc[nt][0]);
                pah[2*half+1] = cvth2(sacc[nt][3], sacc[nt][2]);
            }
            int vrow = kk*16 + vr;
            #pragma unroll
            for (int np = 0; np < 8; np++) {
                int vchk = 2*np + vbit;
                unsigned vaddr = smem_u + kvcur + 8192u
                               + (unsigned)(vrow*16 + (vchk ^ (vrow&7)))*16;
                unsigned vbh[4];
                ldsm4t(vbh, vaddr);
                mma16816h(o[2*np],   pah, vbh);
                mma16816h(o[2*np+1], pah, vbh+2);
            }
        }
        __syncthreads();
    }

    // epilogue: normalize, write single fp16 plane of O
    float inv0 = 1.f / (l0s + 1e-12f);
    float inv1 = 1.f / (l1s + 1e-12f);
    int r0 = q0 + wq0 + g;
    size_t base0 = ((size_t)(b_*SS + r0))*HD + h*DD;
    size_t base1 = base0 + (size_t)8*HD;
    #pragma unroll
    for (int nt = 0; nt < 16; nt++) {
        int cc = nt*8 + 2*tig;
        *(unsigned*)(g_O + base0 + cc) = cvth2(o[nt][1]*inv0, o[nt][0]*inv0);
        *(unsigned*)(g_O + base1 + cc) = cvth2(o[nt][3]*inv1, o[nt][2]*inv1);
    }
}

// ---------------------------------------------------------------------------
// Output projection (validated r12): fp16 mma, 64x64 tiles, double-buffered.
// ---------------------------------------------------------------------------
__global__ __launch_bounds__(256) void out_proj_kernel(
    const float* __restrict__ bc, float* __restrict__ out)
{
    extern __shared__ char smo[];
    const unsigned su = (unsigned)__cvta_generic_to_shared(smo);

    const int m0 = blockIdx.x * 64;
    const int n0 = blockIdx.y * 64;
    const int tid = threadIdx.x;
    const int lane = tid & 31;
    const int wid  = tid >> 5;
    const int mrow0 = (wid & 3)*16;
    const int ncol0 = (wid >> 2)*32;
    const int g = lane >> 2, tig = lane & 3;

    const int arow = mrow0 + (lane & 7) + ((lane >> 3) & 1)*8;
    const int abit = lane >> 4;
    const int kb   = (lane & 7) + ((lane >> 4) & 1)*8;
    const int kbit = (lane >> 3) & 1;

    float acc[4][4];
    #pragma unroll
    for (int nt = 0; nt < 4; nt++)
        #pragma unroll
        for (int c = 0; c < 4; c++) acc[nt][c] = 0.f;

    const uint4* Ap = (const uint4*)g_O;
    const uint4* Bp = (const uint4*)g_Wc;

    {
        #pragma unroll
        for (int t = 0; t < 4; t++) {
            int idx = tid + 256*t;
            int r = idx >> 4, c = idx & 15;
            unsigned sw = (unsigned)(r*16 + (c^(r&7)))*16;
            cpa(su + sw,          Ap + (size_t)(m0+r)*(HD/8) + c);
            cpa(su + 16384u + sw, Bp + (size_t)(n0+r)*(HD/8) + c);
        }
        cpa_commit();
    }

    for (int i = 0; i < 8; i++) {
        const unsigned cur = (unsigned)(i & 1) * 32768u;
        if (i < 7) {
            const unsigned nxt = (unsigned)((i+1) & 1) * 32768u;
            int kc8 = (i+1) * 16;
            #pragma unroll
            for (int t = 0; t < 4; t++) {
                int idx = tid + 256*t;
                int r = idx >> 4, c = idx & 15;
                unsigned sw = (unsigned)(r*16 + (c^(r&7)))*16;
                cpa(su + nxt + sw,          Ap + (size_t)(m0+r)*(HD/8) + kc8 + c);
                cpa(su + nxt + 16384u + sw, Bp + (size_t)(n0+r)*(HD/8) + kc8 + c);
            }
            cpa_commit();
            cpa_wait<1>();
        } else {
            cpa_wait<0>();
        }
        __syncthreads();

        #pragma unroll
        for (int ks = 0; ks < 8; ks++) {
            unsigned a_h[4];
            unsigned aaddr = su + cur + (unsigned)(arow*16 + ((2*ks+abit) ^ (arow&7)))*16;
            ldsm4(a_h, aaddr);
            unsigned bh_[2][4];
            #pragma unroll
            for (int np = 0; np < 2; np++) {
                int brow = ncol0 + np*16 + kb;
                unsigned baddr = su + cur + 16384u + (unsigned)(brow*16 + ((2*ks+kbit) ^ (brow&7)))*16;
                ldsm4(bh_[np], baddr);
            }
            #pragma unroll
            for (int np = 0; np < 2; np++) {
                mma16816h(acc[2*np],   a_h, bh_[np]);
                mma16816h(acc[2*np+1], a_h, bh_[np]+2);
            }
        }
        __syncthreads();
    }

    #pragma unroll
    for (int nt = 0; nt < 4; nt++) {
        int n = n0 + ncol0 + nt*8 + 2*tig;
        float2 bb = *(const float2*)(bc + n);
        int ma = m0 + mrow0 + g;
        *(float2*)(out + (size_t)ma*128 + n) =
            make_float2(acc[nt][0] + bb.x, acc[nt][1] + bb.y);
        *(float2*)(out + (size_t)(ma+8)*128 + n) =
            make_float2(acc[nt][2] + bb.x, acc[nt][3] + bb.y);
    }
}

// ---------------------------------------------------------------------------
extern "C" void kernel_launch(void* const* d_in, const int* in_sizes, int n_in,
                              void* d_out, int out_size)
{
    const float* q    = (const float*)d_in[0];
    const float* k    = (const float*)d_in[1];
    const float* v    = (const float*)d_in[2];
    const float* mask = (const float*)d_in[3];
    const float* Wq   = (const float*)d_in[4];
    const float* Wk   = (const float*)d_in[5];
    const float* Wv   = (const float*)d_in[6];
    const float* Wc   = (const float*)d_in[7];
    const float* bc   = (const float*)d_in[8];
    float* out = (float*)d_out;

    const int qkv_smem  = 49152;
    const int attn_smem = 69632;
    const int outp_smem = 65536;

    cudaFuncSetAttribute(qkv_proj_kernel, cudaFuncAttributeMaxDynamicSharedMemorySize, qkv_smem);
    cudaFuncSetAttribute(attn_kernel, cudaFuncAttributeMaxDynamicSharedMemorySize, attn_smem);
    cudaFuncSetAttribute(out_proj_kernel, cudaFuncAttributeMaxDynamicSharedMemorySize, outp_smem);

    convert_kernel<<<dim3(96, 7), 256>>>(q, k, v, Wq, Wk, Wv, Wc);
    qkv_proj_kernel<<<dim3(8, 128, 3), 256, qkv_smem>>>();
    attn_kernel<<<dim3(8, 64), 256, attn_smem>>>(mask);
    out_proj_kernel<<<dim3(128, 2), 256, outp_smem>>>(bc, out);
}

// round 15
// speedup vs baseline: 1.3734x; 1.3734x over previous
#include <cuda_runtime.h>
#include <cuda_bf16.h>
#include <cuda_fp16.h>

#define BB 8
#define SS 1024
#define HH 8
#define DD 128
#define HD 1024

// ---- scratch planes (fp16) ----
__device__ __half g_Wc[128*HD];
__device__ __half g_Q[(size_t)BB*HH*SS*DD];
__device__ __half g_K[(size_t)BB*HH*SS*DD];
__device__ __half g_V[(size_t)BB*HH*SS*DD];
__device__ __half g_O[(size_t)BB*SS*HD];

// ---- helpers ----
__device__ __forceinline__ void mma16816h(float* c, const unsigned* a, const unsigned* b) {
    asm volatile(
        "mma.sync.aligned.m16n8k16.row.col.f32.f16.f16.f32 "
        "{%0,%1,%2,%3}, {%4,%5,%6,%7}, {%8,%9}, {%0,%1,%2,%3};\n"
        : "+f"(c[0]), "+f"(c[1]), "+f"(c[2]), "+f"(c[3])
        : "r"(a[0]), "r"(a[1]), "r"(a[2]), "r"(a[3]), "r"(b[0]), "r"(b[1]));
}
__device__ __forceinline__ void mma16816hh(unsigned* c, const unsigned* a, const unsigned* b) {
    asm volatile(
        "mma.sync.aligned.m16n8k16.row.col.f16.f16.f16.f16 "
        "{%0,%1}, {%2,%3,%4,%5}, {%6,%7}, {%0,%1};\n"
        : "+r"(c[0]), "+r"(c[1])
        : "r"(a[0]), "r"(a[1]), "r"(a[2]), "r"(a[3]), "r"(b[0]), "r"(b[1]));
}
__device__ __forceinline__ void ldsm4(unsigned* r, unsigned addr) {
    asm volatile("ldmatrix.sync.aligned.m8n8.x4.shared.b16 {%0,%1,%2,%3}, [%4];"
        : "=r"(r[0]), "=r"(r[1]), "=r"(r[2]), "=r"(r[3]) : "r"(addr));
}
__device__ __forceinline__ void ldsm4t(unsigned* r, unsigned addr) {
    asm volatile("ldmatrix.sync.aligned.m8n8.x4.trans.shared.b16 {%0,%1,%2,%3}, [%4];"
        : "=r"(r[0]), "=r"(r[1]), "=r"(r[2]), "=r"(r[3]) : "r"(addr));
}
__device__ __forceinline__ unsigned cvth2(float hi, float lo) {
    unsigned r;
    asm("cvt.rn.f16x2.f32 %0, %1, %2;" : "=r"(r) : "f"(hi), "f"(lo));
    return r;
}
__device__ __forceinline__ void cpa(unsigned dst, const void* src) {
    asm volatile("cp.async.cg.shared.global [%0], [%1], 16;" :: "r"(dst), "l"(src));
}
__device__ __forceinline__ void cpa_commit() { asm volatile("cp.async.commit_group;"); }
template<int N> __device__ __forceinline__ void cpa_wait() {
    asm volatile("cp.async.wait_group %0;" :: "n"(N));
}

// ---------------------------------------------------------------------------
// Convert Wc (fp32 -> fp16), tiny one-time kernel.
// ---------------------------------------------------------------------------
__global__ __launch_bounds__(256) void convert_kernel(const float* __restrict__ Wc)
{
    int n4 = 128*HD/4;
    for (int i = blockIdx.x*256 + threadIdx.x; i < n4; i += gridDim.x*256) {
        float4 f = ((const float4*)Wc)[i];
        ((uint2*)g_Wc)[i] = make_uint2(cvth2(f.y, f.x), cvth2(f.w, f.z));
    }
}

// ---------------------------------------------------------------------------
// Fused QKV projection: fp32 inputs converted in-kernel to fp16 smem tiles.
// CTA tile 64(M) x 128(N=head), K=128. 256 thr, 8 warps.
// smem: A 0 (16KB), B 16384 (32KB) -> 48KB.
// ---------------------------------------------------------------------------
__global__ __launch_bounds__(256) void qkv_proj_kernel(
    const float* __restrict__ q, const float* __restrict__ k, const float* __restrict__ v,
    const float* __restrict__ Wq, const float* __restrict__ Wk, const float* __restrict__ Wv)
{
    extern __shared__ char smq[];
    const unsigned su = (unsigned)__cvta_generic_to_shared(smq);

    const float *Xf, *Wf;
    __half* Oh;
    if (blockIdx.z == 0)      { Xf = q; Wf = Wq; Oh = g_Q; }
    else if (blockIdx.z == 1) { Xf = k; Wf = Wk; Oh = g_K; }
    else                      { Xf = v; Wf = Wv; Oh = g_V; }

    const int m0 = blockIdx.y * 64;
    const int h  = blockIdx.x;
    const int tid = threadIdx.x;
    const int lane = tid & 31;
    const int wid  = tid >> 5;
    const int band = wid & 3, side = wid >> 2;
    const int g    = lane >> 2, tig = lane & 3;

    // A tile: 64 rows x 16 chunks (8 fp16/chunk). Load fp32, convert, store.
    #pragma unroll
    for (int t = 0; t < 4; t++) {
        int idx = tid + 256*t;
        int r = idx >> 4, c = idx & 15;
        const float4* p = (const float4*)(Xf + (size_t)(m0+r)*128 + c*8);
        float4 f0 = p[0], f1 = p[1];
        *(uint4*)(smq + (r*16 + (c^(r&7)))*16) =
            make_uint4(cvth2(f0.y,f0.x), cvth2(f0.w,f0.z),
                       cvth2(f1.y,f1.x), cvth2(f1.w,f1.z));
    }
    // B tile: 128 rows x 16 chunks
    #pragma unroll
    for (int t = 0; t < 8; t++) {
        int idx = tid + 256*t;
        int r = idx >> 4, c = idx & 15;
        const float4* p = (const float4*)(Wf + (size_t)(h*128+r)*128 + c*8);
        float4 f0 = p[0], f1 = p[1];
        *(uint4*)(smq + 16384 + (r*16 + (c^(r&7)))*16) =
            make_uint4(cvth2(f0.y,f0.x), cvth2(f0.w,f0.z),
                       cvth2(f1.y,f1.x), cvth2(f1.w,f1.z));
    }
    __syncthreads();

    float acc[8][4];
    #pragma unroll
    for (int nt = 0; nt < 8; nt++)
        #pragma unroll
        for (int c = 0; c < 4; c++) acc[nt][c] = 0.f;

    const int arow = band*16 + (lane & 7) + ((lane >> 3) & 1)*8;
    const int abit = lane >> 4;
    const int kb   = (lane & 7) + ((lane >> 4) & 1)*8;
    const int kbit = (lane >> 3) & 1;

    #pragma unroll
    for (int ks = 0; ks < 8; ks++) {
        unsigned a_h[4];
        unsigned aaddr = su + (unsigned)(arow*16 + ((2*ks+abit) ^ (arow&7)))*16;
        ldsm4(a_h, aaddr);
        unsigned bh_[4][4];
        #pragma unroll
        for (int np = 0; np < 4; np++) {
            int brow = side*64 + np*16 + kb;
            unsigned baddr = su + 16384u + (unsigned)(brow*16 + ((2*ks+kbit) ^ (brow&7)))*16;
            ldsm4(bh_[np], baddr);
        }
        #pragma unroll
        for (int np = 0; np < 4; np++) {
            mma16816h(acc[2*np],   a_h, bh_[np]);
            mma16816h(acc[2*np+1], a_h, bh_[np]+2);
        }
    }

    // epilogue: single fp16 plane at [B,H,S,D]
    #pragma unroll
    for (int nt = 0; nt < 8; nt++) {
        int col = side*64 + nt*8 + 2*tig;
        int ma = m0 + band*16 + g;
        int mb2 = ma + 8;
        size_t offa = (((size_t)((ma  >> 10)*HH + h))*SS + (ma  & 1023))*DD + col;
        size_t offb = (((size_t)((mb2 >> 10)*HH + h))*SS + (mb2 & 1023))*DD + col;
        *(unsigned*)(Oh + offa) = cvth2(acc[nt][1], acc[nt][0]);
        *(unsigned*)(Oh + offb) = cvth2(acc[nt][3], acc[nt][2]);
    }
}

// ---------------------------------------------------------------------------
// Flash attention (validated r12): QK fp16-accum, PV fp16 w/ fp32 accum.
// 256 thr / 8 warps, cp.async double-buffered K/V, 2 CTAs/SM.
// smem: msk 0 (4KB), Q 4096 (32KB), KV0 36864 (32KB: K+0, V+16384),
//       KV1 69632 (32KB). Total 100KB.
// ---------------------------------------------------------------------------
__global__ __launch_bounds__(256, 2) void attn_kernel(const float* __restrict__ mask)
{
    extern __shared__ char sm[];
    float* msk_s = (float*)sm;
    const unsigned smem_u = (unsigned)__cvta_generic_to_shared(sm);
    const unsigned offQh = 4096u, KV0 = 36864u, KV1 = 69632u;

    const int tid  = threadIdx.x;
    const int lane = tid & 31;
    const int wid  = tid >> 5;
    const int wq0  = wid * 16;
    const int g    = lane >> 2;
    const int tig  = lane & 3;

    const int bh = blockIdx.y;
    const int b_ = bh >> 3, h = bh & 7;
    const int q0 = blockIdx.x * 128;

    const uint4* qh4 = (const uint4*)(g_Q + ((size_t)bh*SS + q0)*DD);
    const uint4* kh4 = (const uint4*)(g_K + (size_t)bh*SS*DD);
    const uint4* vh4 = (const uint4*)(g_V + (size_t)bh*SS*DD);
    const float* mb = mask + b_*SS;

    *(float4*)&msk_s[tid*4] = ((const float4*)mb)[tid];
    #pragma unroll
    for (int t = 0; t < 8; t++) {
        int idx = tid + 256*t;
        int r = idx >> 4, c = idx & 15;
        unsigned phys = (unsigned)(r*16 + (c ^ (r&7)))*16;
        *(uint4*)(sm + 4096 + phys) = qh4[idx];
    }
    {
        #pragma unroll
        for (int t = 0; t < 4; t++) {
            int idx = tid + 256*t;
            int r = idx >> 4, c = idx & 15;
            unsigned dst = smem_u + KV0 + (unsigned)(r*16 + (c^(r&7)))*16;
            cpa(dst,          kh4 + idx);
            cpa(dst + 16384u, vh4 + idx);
        }
        cpa_commit();
    }

    float o[16][4];
    #pragma unroll
    for (int nt = 0; nt < 16; nt++)
        #pragma unroll
        for (int c = 0; c < 4; c++) o[nt][c] = 0.f;

    float m0s = -3.0e38f, m1s = -3.0e38f, l0s = 0.f, l1s = 0.f;
    const float scale = 0.08838834764831845f;  // 1/sqrt(128)

    const int arow = wq0 + (lane & 7) + ((lane >> 3) & 1)*8;
    const int abit = lane >> 4;
    const int kbr  = (lane & 7) + ((lane >> 4) & 1)*8;
    const int kbit = (lane >> 3) & 1;
    const int vr   = (lane & 7) + ((lane >> 3) & 1)*8;
    const int vbit = (lane >> 4) & 1;

    for (int it = 0; it < 16; it++) {
        const int j0 = it*64;
        const unsigned kvcur = (it & 1) ? KV1 : KV0;
        if (it < 15) {
            const unsigned kvnxt = (it & 1) ? KV0 : KV1;
            #pragma unroll
            for (int t = 0; t < 4; t++) {
                int idx = tid + 256*t;
                int r = idx >> 4, c = idx & 15;
                unsigned dst = smem_u + kvnxt + (unsigned)(r*16 + (c^(r&7)))*16;
                int gi = (j0 + 64 + r)*16 + c;
                cpa(dst,          kh4 + gi);
                cpa(dst + 16384u, vh4 + gi);
            }
            cpa_commit();
            cpa_wait<1>();
        } else {
            cpa_wait<0>();
        }
        __syncthreads();

        // ---- S = Q K^T (fp16 accumulator, packed) ----
        unsigned sph[8][2];
        #pragma unroll
        for (int nt = 0; nt < 8; nt++) { sph[nt][0] = 0u; sph[nt][1] = 0u; }

        #pragma unroll
        for (int ks = 0; ks < 8; ks++) {
            unsigned a_h[4];
            unsigned aaddr = smem_u + offQh + (unsigned)(arow*16 + ((2*ks+abit) ^ (arow&7)))*16;
            ldsm4(a_h, aaddr);
            unsigned bh_[4][4];
            #pragma unroll
            for (int np = 0; np < 4; np++) {
                int brow = np*16 + kbr;
                unsigned baddr = smem_u + kvcur + (unsigned)(brow*16 + ((2*ks+kbit) ^ (brow&7)))*16;
                ldsm4(bh_[np], baddr);
            }
            #pragma unroll
            for (int np = 0; np < 4; np++) {
                mma16816hh(sph[2*np],   a_h, bh_[np]);
                mma16816hh(sph[2*np+1], a_h, bh_[np]+2);
            }
        }

        // unpack to fp32
        float sacc[8][4];
        #pragma unroll
        for (int nt = 0; nt < 8; nt++) {
            float2 f01 = __half22float2(*(__half2*)&sph[nt][0]);
            float2 f23 = __half22float2(*(__half2*)&sph[nt][1]);
            sacc[nt][0] = f01.x; sacc[nt][1] = f01.y;
            sacc[nt][2] = f23.x; sacc[nt][3] = f23.y;
        }

        // ---- online softmax ----
        float mx0 = -3.0e38f, mx1 = -3.0e38f;
        #pragma unroll
        for (int nt = 0; nt < 8; nt++) {
            float2 mk = *(float2*)&msk_s[j0 + nt*8 + 2*tig];
            sacc[nt][0] = sacc[nt][0]*scale + mk.x;
            sacc[nt][1] = sacc[nt][1]*scale + mk.y;
            sacc[nt][2] = sacc[nt][2]*scale + mk.x;
            sacc[nt][3] = sacc[nt][3]*scale + mk.y;
            mx0 = fmaxf(mx0, fmaxf(sacc[nt][0], sacc[nt][1]));
            mx1 = fmaxf(mx1, fmaxf(sacc[nt][2], sacc[nt][3]));
        }
        #pragma unroll
        for (int mskb = 1; mskb <= 2; mskb <<= 1) {
            mx0 = fmaxf(mx0, __shfl_xor_sync(0xffffffffu, mx0, mskb));
            mx1 = fmaxf(mx1, __shfl_xor_sync(0xffffffffu, mx1, mskb));
        }
        float mn0 = fmaxf(m0s, mx0), mn1 = fmaxf(m1s, mx1);
        float al0 = __expf(m0s - mn0), al1 = __expf(m1s - mn1);
        m0s = mn0; m1s = mn1;

        float sum0 = 0.f, sum1 = 0.f;
        #pragma unroll
        for (int nt = 0; nt < 8; nt++) {
            float p0 = __expf(sacc[nt][0] - mn0);
            float p1 = __expf(sacc[nt][1] - mn0);
            float p2 = __expf(sacc[nt][2] - mn1);
            float p3 = __expf(sacc[nt][3] - mn1);
            sacc[nt][0] = p0; sacc[nt][1] = p1; sacc[nt][2] = p2; sacc[nt][3] = p3;
            sum0 += p0 + p1; sum1 += p2 + p3;
        }
        #pragma unroll
        for (int mskb = 1; mskb <= 2; mskb <<= 1) {
            sum0 += __shfl_xor_sync(0xffffffffu, sum0, mskb);
            sum1 += __shfl_xor_sync(0xffffffffu, sum1, mskb);
        }
        l0s = l0s*al0 + sum0;
        l1s = l1s*al1 + sum1;

        #pragma unroll
        for (int nt = 0; nt < 16; nt++) {
            o[nt][0] *= al0; o[nt][1] *= al0;
            o[nt][2] *= al1; o[nt][3] *= al1;
        }

        // ---- O += P V ----
        #pragma unroll
        for (int kk = 0; kk < 4; kk++) {
            unsigned pah[4];
            #pragma unroll
            for (int half = 0; half < 2; half++) {
                int nt = 2*kk + half;
                pah[2*half]   = cvth2(sacc[nt][1], sacc[nt][0]);
                pah[2*half+1] = cvth2(sacc[nt][3], sacc[nt][2]);
            }
            int vrow = kk*16 + vr;
            #pragma unroll
            for (int np = 0; np < 8; np++) {
                int vchk = 2*np + vbit;
                unsigned vaddr = smem_u + kvcur + 16384u
                               + (unsigned)(vrow*16 + (vchk ^ (vrow&7)))*16;
                unsigned vbh[4];
                ldsm4t(vbh, vaddr);
                mma16816h(o[2*np],   pah, vbh);
                mma16816h(o[2*np+1], pah, vbh+2);
            }
        }
        __syncthreads();
    }

    float inv0 = 1.f / (l0s + 1e-12f);
    float inv1 = 1.f / (l1s + 1e-12f);
    int r0 = q0 + wq0 + g;
    size_t base0 = ((size_t)(b_*SS + r0))*HD + h*DD;
    size_t base1 = base0 + (size_t)8*HD;
    #pragma unroll
    for (int nt = 0; nt < 16; nt++) {
        int cc = nt*8 + 2*tig;
        *(unsigned*)(g_O + base0 + cc) = cvth2(o[nt][1]*inv0, o[nt][0]*inv0);
        *(unsigned*)(g_O + base1 + cc) = cvth2(o[nt][3]*inv1, o[nt][2]*inv1);
    }
}

// ---------------------------------------------------------------------------
// Output projection (validated r12): fp16 mma, 64x64 tiles, double-buffered.
// ---------------------------------------------------------------------------
__global__ __launch_bounds__(256) void out_proj_kernel(
    const float* __restrict__ bc, float* __restrict__ out)
{
    extern __shared__ char smo[];
    const unsigned su = (unsigned)__cvta_generic_to_shared(smo);

    const int m0 = blockIdx.x * 64;
    const int n0 = blockIdx.y * 64;
    const int tid = threadIdx.x;
    const int lane = tid & 31;
    const int wid  = tid >> 5;
    const int mrow0 = (wid & 3)*16;
    const int ncol0 = (wid >> 2)*32;
    const int g = lane >> 2, tig = lane & 3;

    const int arow = mrow0 + (lane & 7) + ((lane >> 3) & 1)*8;
    const int abit = lane >> 4;
    const int kb   = (lane & 7) + ((lane >> 4) & 1)*8;
    const int kbit = (lane >> 3) & 1;

    float acc[4][4];
    #pragma unroll
    for (int nt = 0; nt < 4; nt++)
        #pragma unroll
        for (int c = 0; c < 4; c++) acc[nt][c] = 0.f;

    const uint4* Ap = (const uint4*)g_O;
    const uint4* Bp = (const uint4*)g_Wc;

    {
        #pragma unroll
        for (int t = 0; t < 4; t++) {
            int idx = tid + 256*t;
            int r = idx >> 4, c = idx & 15;
            unsigned sw = (unsigned)(r*16 + (c^(r&7)))*16;
            cpa(su + sw,          Ap + (size_t)(m0+r)*(HD/8) + c);
            cpa(su + 16384u + sw, Bp + (size_t)(n0+r)*(HD/8) + c);
        }
        cpa_commit();
    }

    for (int i = 0; i < 8; i++) {
        const unsigned cur = (unsigned)(i & 1) * 32768u;
        if (i < 7) {
            const unsigned nxt = (unsigned)((i+1) & 1) * 32768u;
            int kc8 = (i+1) * 16;
            #pragma unroll
            for (int t = 0; t < 4; t++) {
                int idx = tid + 256*t;
                int r = idx >> 4, c = idx & 15;
                unsigned sw = (unsigned)(r*16 + (c^(r&7)))*16;
                cpa(su + nxt + sw,          Ap + (size_t)(m0+r)*(HD/8) + kc8 + c);
                cpa(su + nxt + 16384u + sw, Bp + (size_t)(n0+r)*(HD/8) + kc8 + c);
            }
            cpa_commit();
            cpa_wait<1>();
        } else {
            cpa_wait<0>();
        }
        __syncthreads();

        #pragma unroll
        for (int ks = 0; ks < 8; ks++) {
            unsigned a_h[4];
            unsigned aaddr = su + cur + (unsigned)(arow*16 + ((2*ks+abit) ^ (arow&7)))*16;
            ldsm4(a_h, aaddr);
            unsigned bh_[2][4];
            #pragma unroll
            for (int np = 0; np < 2; np++) {
                int brow = ncol0 + np*16 + kb;
                unsigned baddr = su + cur + 16384u + (unsigned)(brow*16 + ((2*ks+kbit) ^ (brow&7)))*16;
                ldsm4(bh_[np], baddr);
            }
            #pragma unroll
            for (int np = 0; np < 2; np++) {
                mma16816h(acc[2*np],   a_h, bh_[np]);
                mma16816h(acc[2*np+1], a_h, bh_[np]+2);
            }
        }
        __syncthreads();
    }

    #pragma unroll
    for (int nt = 0; nt < 4; nt++) {
        int n = n0 + ncol0 + nt*8 + 2*tig;
        float2 bb = *(const float2*)(bc + n);
        int ma = m0 + mrow0 + g;
        *(float2*)(out + (size_t)ma*128 + n) =
            make_float2(acc[nt][0] + bb.x, acc[nt][1] + bb.y);
        *(float2*)(out + (size_t)(ma+8)*128 + n) =
            make_float2(acc[nt][2] + bb.x, acc[nt][3] + bb.y);
    }
}

// ---------------------------------------------------------------------------
extern "C" void kernel_launch(void* const* d_in, const int* in_sizes, int n_in,
                              void* d_out, int out_size)
{
    const float* q    = (const float*)d_in[0];
    const float* k    = (const float*)d_in[1];
    const float* v    = (const float*)d_in[2];
    const float* mask = (const float*)d_in[3];
    const float* Wq   = (const float*)d_in[4];
    const float* Wk   = (const float*)d_in[5];
    const float* Wv   = (const float*)d_in[6];
    const float* Wc   = (const float*)d_in[7];
    const float* bc   = (const float*)d_in[8];
    float* out = (float*)d_out;

    const int qkv_smem  = 49152;
    const int attn_smem = 102400;
    const int outp_smem = 65536;

    cudaFuncSetAttribute(qkv_proj_kernel, cudaFuncAttributeMaxDynamicSharedMemorySize, qkv_smem);
    cudaFuncSetAttribute(attn_kernel, cudaFuncAttributeMaxDynamicSharedMemorySize, attn_smem);
    cudaFuncSetAttribute(out_proj_kernel, cudaFuncAttributeMaxDynamicSharedMemorySize, outp_smem);

    convert_kernel<<<64, 256>>>(Wc);
    qkv_proj_kernel<<<dim3(8, 128, 3), 256, qkv_smem>>>(q, k, v, Wq, Wk, Wv);
    attn_kernel<<<dim3(8, 64), 256, attn_smem>>>(mask);
    out_proj_kernel<<<dim3(128, 2), 256, outp_smem>>>(bc, out);
}

// round 16
// speedup vs baseline: 1.4857x; 1.0818x over previous
#include <cuda_runtime.h>
#include <cuda_bf16.h>
#include <cuda_fp16.h>

#define BB 8
#define SS 1024
#define HH 8
#define DD 128
#define HD 1024

// ---- scratch planes (fp16 payload throughout) ----
__device__ __half g_Xq[(size_t)BB*SS*128];
__device__ __half g_Xk[(size_t)BB*SS*128];
__device__ __half g_Xv[(size_t)BB*SS*128];
__device__ __half g_Wq[HD*128], g_Wk[HD*128], g_Wv[HD*128];
__device__ __half g_Wc[128*HD];
__device__ __half g_Q[(size_t)BB*HH*SS*DD];
__device__ __half g_K[(size_t)BB*HH*SS*DD];
__device__ __half g_V[(size_t)BB*HH*SS*DD];
__device__ __half g_O[(size_t)BB*SS*HD];

// ---- helpers ----
__device__ __forceinline__ void mma16816h(float* c, const unsigned* a, const unsigned* b) {
    asm volatile(
        "mma.sync.aligned.m16n8k16.row.col.f32.f16.f16.f32 "
        "{%0,%1,%2,%3}, {%4,%5,%6,%7}, {%8,%9}, {%0,%1,%2,%3};\n"
        : "+f"(c[0]), "+f"(c[1]), "+f"(c[2]), "+f"(c[3])
        : "r"(a[0]), "r"(a[1]), "r"(a[2]), "r"(a[3]), "r"(b[0]), "r"(b[1]));
}
__device__ __forceinline__ void mma16816hh(unsigned* c, const unsigned* a, const unsigned* b) {
    asm volatile(
        "mma.sync.aligned.m16n8k16.row.col.f16.f16.f16.f16 "
        "{%0,%1}, {%2,%3,%4,%5}, {%6,%7}, {%0,%1};\n"
        : "+r"(c[0]), "+r"(c[1])
        : "r"(a[0]), "r"(a[1]), "r"(a[2]), "r"(a[3]), "r"(b[0]), "r"(b[1]));
}
__device__ __forceinline__ void ldsm4(unsigned* r, unsigned addr) {
    asm volatile("ldmatrix.sync.aligned.m8n8.x4.shared.b16 {%0,%1,%2,%3}, [%4];"
        : "=r"(r[0]), "=r"(r[1]), "=r"(r[2]), "=r"(r[3]) : "r"(addr));
}
__device__ __forceinline__ void ldsm4t(unsigned* r, unsigned addr) {
    asm volatile("ldmatrix.sync.aligned.m8n8.x4.trans.shared.b16 {%0,%1,%2,%3}, [%4];"
        : "=r"(r[0]), "=r"(r[1]), "=r"(r[2]), "=r"(r[3]) : "r"(addr));
}
__device__ __forceinline__ unsigned cvth2(float hi, float lo) {
    unsigned r;
    asm("cvt.rn.f16x2.f32 %0, %1, %2;" : "=r"(r) : "f"(hi), "f"(lo));
    return r;
}
__device__ __forceinline__ void cpa(unsigned dst, const void* src) {
    asm volatile("cp.async.cg.shared.global [%0], [%1], 16;" :: "r"(dst), "l"(src));
}
__device__ __forceinline__ void cpa_commit() { asm volatile("cp.async.commit_group;"); }
template<int N> __device__ __forceinline__ void cpa_wait() {
    asm volatile("cp.async.wait_group %0;" :: "n"(N));
}

// ---------------------------------------------------------------------------
// Convert fp32 operands to single fp16 planes (one-time, memory-bound).
// ---------------------------------------------------------------------------
__global__ __launch_bounds__(256) void convert_kernel(
    const float* __restrict__ q, const float* __restrict__ k, const float* __restrict__ v,
    const float* __restrict__ Wq, const float* __restrict__ Wk, const float* __restrict__ Wv,
    const float* __restrict__ Wc)
{
    const float* src; __half* dh; int n4;
    switch (blockIdx.y) {
        case 0: src = q;  dh = g_Xq; n4 = BB*SS*128/4; break;
        case 1: src = k;  dh = g_Xk; n4 = BB*SS*128/4; break;
        case 2: src = v;  dh = g_Xv; n4 = BB*SS*128/4; break;
        case 3: src = Wq; dh = g_Wq; n4 = HD*128/4; break;
        case 4: src = Wk; dh = g_Wk; n4 = HD*128/4; break;
        case 5: src = Wv; dh = g_Wv; n4 = HD*128/4; break;
        default: src = Wc; dh = g_Wc; n4 = 128*HD/4; break;
    }
    for (int i = blockIdx.x*256 + threadIdx.x; i < n4; i += gridDim.x*256) {
        float4 f = ((const float4*)src)[i];
        ((uint2*)dh)[i] = make_uint2(cvth2(f.y, f.x), cvth2(f.w, f.z));
    }
}

// ---------------------------------------------------------------------------
// Fused QKV projection: single-term fp16 mma.sync, CTA tile 128(M) x 128(N).
// 256 thr, 8 warps; warp = 16 rows x 128 cols. grid (8, 64, 3).
// smem: A 0 (32KB), B 32768 (32KB) -> 64KB, 2 CTAs/SM.
// ---------------------------------------------------------------------------
__global__ __launch_bounds__(256) void qkv_proj_kernel()
{
    extern __shared__ char smq[];
    const unsigned su = (unsigned)__cvta_generic_to_shared(smq);

    const uint4 *Xp, *Wp;
    __half* Oh;
    if (blockIdx.z == 0)      { Xp=(const uint4*)g_Xq; Wp=(const uint4*)g_Wq; Oh=g_Q; }
    else if (blockIdx.z == 1) { Xp=(const uint4*)g_Xk; Wp=(const uint4*)g_Wk; Oh=g_K; }
    else                      { Xp=(const uint4*)g_Xv; Wp=(const uint4*)g_Wv; Oh=g_V; }

    const int m0 = blockIdx.y * 128;
    const int h  = blockIdx.x;
    const int tid = threadIdx.x;
    const int lane = tid & 31;
    const int wid  = tid >> 5;
    const int g    = lane >> 2, tig = lane & 3;

    #pragma unroll
    for (int t = 0; t < 8; t++) {
        int idx = tid + 256*t;
        int r = idx >> 4, c = idx & 15;
        unsigned sw = (unsigned)(r*16 + (c^(r&7)))*16;
        cpa(su + sw,          Xp + (size_t)(m0+r)*16 + c);
        cpa(su + 32768u + sw, Wp + (size_t)(h*128+r)*16 + c);
    }
    cpa_commit();
    cpa_wait<0>();
    __syncthreads();

    float acc[16][4];
    #pragma unroll
    for (int nt = 0; nt < 16; nt++)
        #pragma unroll
        for (int c = 0; c < 4; c++) acc[nt][c] = 0.f;

    const int arow = wid*16 + (lane & 7) + ((lane >> 3) & 1)*8;
    const int abit = lane >> 4;
    const int kb   = (lane & 7) + ((lane >> 4) & 1)*8;
    const int kbit = (lane >> 3) & 1;

    #pragma unroll
    for (int ks = 0; ks < 8; ks++) {
        unsigned a_h[4];
        unsigned aaddr = su + (unsigned)(arow*16 + ((2*ks+abit) ^ (arow&7)))*16;
        ldsm4(a_h, aaddr);
        #pragma unroll
        for (int np = 0; np < 8; np++) {
            int brow = np*16 + kb;
            unsigned baddr = su + 32768u + (unsigned)(brow*16 + ((2*ks+kbit) ^ (brow&7)))*16;
            unsigned bh_[4];
            ldsm4(bh_, baddr);
            mma16816h(acc[2*np],   a_h, bh_);
            mma16816h(acc[2*np+1], a_h, bh_+2);
        }
    }

    // epilogue: single fp16 plane at [B,H,S,D]
    #pragma unroll
    for (int nt = 0; nt < 16; nt++) {
        int col = nt*8 + 2*tig;
        int ma = m0 + wid*16 + g;
        int mb2 = ma + 8;
        size_t offa = (((size_t)((ma  >> 10)*HH + h))*SS + (ma  & 1023))*DD + col;
        size_t offb = (((size_t)((mb2 >> 10)*HH + h))*SS + (mb2 & 1023))*DD + col;
        *(unsigned*)(Oh + offa) = cvth2(acc[nt][1], acc[nt][0]);
        *(unsigned*)(Oh + offb) = cvth2(acc[nt][3], acc[nt][2]);
    }
}

// ---------------------------------------------------------------------------
// Flash attention (validated r12): QK fp16-accum, PV fp16 w/ fp32 accum.
// 256 thr / 8 warps, cp.async double-buffered K/V, 2 CTAs/SM.
// smem: msk 0 (4KB), Q 4096 (32KB), KV0 36864 (32KB: K+0, V+16384),
//       KV1 69632 (32KB). Total 100KB.
// ---------------------------------------------------------------------------
__global__ __launch_bounds__(256, 2) void attn_kernel(const float* __restrict__ mask)
{
    extern __shared__ char sm[];
    float* msk_s = (float*)sm;
    const unsigned smem_u = (unsigned)__cvta_generic_to_shared(sm);
    const unsigned offQh = 4096u, KV0 = 36864u, KV1 = 69632u;

    const int tid  = threadIdx.x;
    const int lane = tid & 31;
    const int wid  = tid >> 5;
    const int wq0  = wid * 16;
    const int g    = lane >> 2;
    const int tig  = lane & 3;

    const int bh = blockIdx.y;
    const int b_ = bh >> 3, h = bh & 7;
    const int q0 = blockIdx.x * 128;

    const uint4* qh4 = (const uint4*)(g_Q + ((size_t)bh*SS + q0)*DD);
    const uint4* kh4 = (const uint4*)(g_K + (size_t)bh*SS*DD);
    const uint4* vh4 = (const uint4*)(g_V + (size_t)bh*SS*DD);
    const float* mb = mask + b_*SS;

    *(float4*)&msk_s[tid*4] = ((const float4*)mb)[tid];
    #pragma unroll
    for (int t = 0; t < 8; t++) {
        int idx = tid + 256*t;
        int r = idx >> 4, c = idx & 15;
        unsigned phys = (unsigned)(r*16 + (c ^ (r&7)))*16;
        *(uint4*)(sm + 4096 + phys) = qh4[idx];
    }
    {
        #pragma unroll
        for (int t = 0; t < 4; t++) {
            int idx = tid + 256*t;
            int r = idx >> 4, c = idx & 15;
            unsigned dst = smem_u + KV0 + (unsigned)(r*16 + (c^(r&7)))*16;
            cpa(dst,          kh4 + idx);
            cpa(dst + 16384u, vh4 + idx);
        }
        cpa_commit();
    }

    float o[16][4];
    #pragma unroll
    for (int nt = 0; nt < 16; nt++)
        #pragma unroll
        for (int c = 0; c < 4; c++) o[nt][c] = 0.f;

    float m0s = -3.0e38f, m1s = -3.0e38f, l0s = 0.f, l1s = 0.f;
    const float scale = 0.08838834764831845f;  // 1/sqrt(128)

    const int arow = wq0 + (lane & 7) + ((lane >> 3) & 1)*8;
    const int abit = lane >> 4;
    const int kbr  = (lane & 7) + ((lane >> 4) & 1)*8;
    const int kbit = (lane >> 3) & 1;
    const int vr   = (lane & 7) + ((lane >> 3) & 1)*8;
    const int vbit = (lane >> 4) & 1;

    for (int it = 0; it < 16; it++) {
        const int j0 = it*64;
        const unsigned kvcur = (it & 1) ? KV1 : KV0;
        if (it < 15) {
            const unsigned kvnxt = (it & 1) ? KV0 : KV1;
            #pragma unroll
            for (int t = 0; t < 4; t++) {
                int idx = tid + 256*t;
                int r = idx >> 4, c = idx & 15;
                unsigned dst = smem_u + kvnxt + (unsigned)(r*16 + (c^(r&7)))*16;
                int gi = (j0 + 64 + r)*16 + c;
                cpa(dst,          kh4 + gi);
                cpa(dst + 16384u, vh4 + gi);
            }
            cpa_commit();
            cpa_wait<1>();
        } else {
            cpa_wait<0>();
        }
        __syncthreads();

        // ---- S = Q K^T (fp16 accumulator, packed) ----
        unsigned sph[8][2];
        #pragma unroll
        for (int nt = 0; nt < 8; nt++) { sph[nt][0] = 0u; sph[nt][1] = 0u; }

        #pragma unroll
        for (int ks = 0; ks < 8; ks++) {
            unsigned a_h[4];
            unsigned aaddr = smem_u + offQh + (unsigned)(arow*16 + ((2*ks+abit) ^ (arow&7)))*16;
            ldsm4(a_h, aaddr);
            unsigned bh_[4][4];
            #pragma unroll
            for (int np = 0; np < 4; np++) {
                int brow = np*16 + kbr;
                unsigned baddr = smem_u + kvcur + (unsigned)(brow*16 + ((2*ks+kbit) ^ (brow&7)))*16;
                ldsm4(bh_[np], baddr);
            }
            #pragma unroll
            for (int np = 0; np < 4; np++) {
                mma16816hh(sph[2*np],   a_h, bh_[np]);
                mma16816hh(sph[2*np+1], a_h, bh_[np]+2);
            }
        }

        // unpack to fp32
        float sacc[8][4];
        #pragma unroll
        for (int nt = 0; nt < 8; nt++) {
            float2 f01 = __half22float2(*(__half2*)&sph[nt][0]);
            float2 f23 = __half22float2(*(__half2*)&sph[nt][1]);
            sacc[nt][0] = f01.x; sacc[nt][1] = f01.y;
            sacc[nt][2] = f23.x; sacc[nt][3] = f23.y;
        }

        // ---- online softmax ----
        float mx0 = -3.0e38f, mx1 = -3.0e38f;
        #pragma unroll
        for (int nt = 0; nt < 8; nt++) {
            float2 mk = *(float2*)&msk_s[j0 + nt*8 + 2*tig];
            sacc[nt][0] = sacc[nt][0]*scale + mk.x;
            sacc[nt][1] = sacc[nt][1]*scale + mk.y;
            sacc[nt][2] = sacc[nt][2]*scale + mk.x;
            sacc[nt][3] = sacc[nt][3]*scale + mk.y;
            mx0 = fmaxf(mx0, fmaxf(sacc[nt][0], sacc[nt][1]));
            mx1 = fmaxf(mx1, fmaxf(sacc[nt][2], sacc[nt][3]));
        }
        #pragma unroll
        for (int mskb = 1; mskb <= 2; mskb <<= 1) {
            mx0 = fmaxf(mx0, __shfl_xor_sync(0xffffffffu, mx0, mskb));
            mx1 = fmaxf(mx1, __shfl_xor_sync(0xffffffffu, mx1, mskb));
        }
        float mn0 = fmaxf(m0s, mx0), mn1 = fmaxf(m1s, mx1);
        float al0 = __expf(m0s - mn0), al1 = __expf(m1s - mn1);
        m0s = mn0; m1s = mn1;

        float sum0 = 0.f, sum1 = 0.f;
        #pragma unroll
        for (int nt = 0; nt < 8; nt++) {
            float p0 = __expf(sacc[nt][0] - mn0);
            float p1 = __expf(sacc[nt][1] - mn0);
            float p2 = __expf(sacc[nt][2] - mn1);
            float p3 = __expf(sacc[nt][3] - mn1);
            sacc[nt][0] = p0; sacc[nt][1] = p1; sacc[nt][2] = p2; sacc[nt][3] = p3;
            sum0 += p0 + p1; sum1 += p2 + p3;
        }
        #pragma unroll
        for (int mskb = 1; mskb <= 2; mskb <<= 1) {
            sum0 += __shfl_xor_sync(0xffffffffu, sum0, mskb);
            sum1 += __shfl_xor_sync(0xffffffffu, sum1, mskb);
        }
        l0s = l0s*al0 + sum0;
        l1s = l1s*al1 + sum1;

        #pragma unroll
        for (int nt = 0; nt < 16; nt++) {
            o[nt][0] *= al0; o[nt][1] *= al0;
            o[nt][2] *= al1; o[nt][3] *= al1;
        }

        // ---- O += P V ----
        #pragma unroll
        for (int kk = 0; kk < 4; kk++) {
            unsigned pah[4];
            #pragma unroll
            for (int half = 0; half < 2; half++) {
                int nt = 2*kk + half;
                pah[2*half]   = cvth2(sacc[nt][1], sacc[nt][0]);
                pah[2*half+1] = cvth2(sacc[nt][3], sacc[nt][2]);
            }
            int vrow = kk*16 + vr;
            #pragma unroll
            for (int np = 0; np < 8; np++) {
                int vchk = 2*np + vbit;
                unsigned vaddr = smem_u + kvcur + 16384u
                               + (unsigned)(vrow*16 + (vchk ^ (vrow&7)))*16;
                unsigned vbh[4];
                ldsm4t(vbh, vaddr);
                mma16816h(o[2*np],   pah, vbh);
                mma16816h(o[2*np+1], pah, vbh+2);
            }
        }
        __syncthreads();
    }

    float inv0 = 1.f / (l0s + 1e-12f);
    float inv1 = 1.f / (l1s + 1e-12f);
    int r0 = q0 + wq0 + g;
    size_t base0 = ((size_t)(b_*SS + r0))*HD + h*DD;
    size_t base1 = base0 + (size_t)8*HD;
    #pragma unroll
    for (int nt = 0; nt < 16; nt++) {
        int cc = nt*8 + 2*tig;
        *(unsigned*)(g_O + base0 + cc) = cvth2(o[nt][1]*inv0, o[nt][0]*inv0);
        *(unsigned*)(g_O + base1 + cc) = cvth2(o[nt][3]*inv1, o[nt][2]*inv1);
    }
}

// ---------------------------------------------------------------------------
// Output projection (validated r12): fp16 mma, 64x64 tiles, double-buffered.
// ---------------------------------------------------------------------------
__global__ __launch_bounds__(256) void out_proj_kernel(
    const float* __restrict__ bc, float* __restrict__ out)
{
    extern __shared__ char smo[];
    const unsigned su = (unsigned)__cvta_generic_to_shared(smo);

    const int m0 = blockIdx.x * 64;
    const int n0 = blockIdx.y * 64;
    const int tid = threadIdx.x;
    const int lane = tid & 31;
    const int wid  = tid >> 5;
    const int mrow0 = (wid & 3)*16;
    const int ncol0 = (wid >> 2)*32;
    const int g = lane >> 2, tig = lane & 3;

    const int arow = mrow0 + (lane & 7) + ((lane >> 3) & 1)*8;
    const int abit = lane >> 4;
    const int kb   = (lane & 7) + ((lane >> 4) & 1)*8;
    const int kbit = (lane >> 3) & 1;

    float acc[4][4];
    #pragma unroll
    for (int nt = 0; nt < 4; nt++)
        #pragma unroll
        for (int c = 0; c < 4; c++) acc[nt][c] = 0.f;

    const uint4* Ap = (const uint4*)g_O;
    const uint4* Bp = (const uint4*)g_Wc;

    {
        #pragma unroll
        for (int t = 0; t < 4; t++) {
            int idx = tid + 256*t;
            int r = idx >> 4, c = idx & 15;
            unsigned sw = (unsigned)(r*16 + (c^(r&7)))*16;
            cpa(su + sw,          Ap + (size_t)(m0+r)*(HD/8) + c);
            cpa(su + 16384u + sw, Bp + (size_t)(n0+r)*(HD/8) + c);
        }
        cpa_commit();
    }

    for (int i = 0; i < 8; i++) {
        const unsigned cur = (unsigned)(i & 1) * 32768u;
        if (i < 7) {
            const unsigned nxt = (unsigned)((i+1) & 1) * 32768u;
            int kc8 = (i+1) * 16;
            #pragma unroll
            for (int t = 0; t < 4; t++) {
                int idx = tid + 256*t;
                int r = idx >> 4, c = idx & 15;
                unsigned sw = (unsigned)(r*16 + (c^(r&7)))*16;
                cpa(su + nxt + sw,          Ap + (size_t)(m0+r)*(HD/8) + kc8 + c);
                cpa(su + nxt + 16384u + sw, Bp + (size_t)(n0+r)*(HD/8) + kc8 + c);
            }
            cpa_commit();
            cpa_wait<1>();
        } else {
            cpa_wait<0>();
        }
        __syncthreads();

        #pragma unroll
        for (int ks = 0; ks < 8; ks++) {
            unsigned a_h[4];
            unsigned aaddr = su + cur + (unsigned)(arow*16 + ((2*ks+abit) ^ (arow&7)))*16;
            ldsm4(a_h, aaddr);
            unsigned bh_[2][4];
            #pragma unroll
            for (int np = 0; np < 2; np++) {
                int brow = ncol0 + np*16 + kb;
                unsigned baddr = su + cur + 16384u + (unsigned)(brow*16 + ((2*ks+kbit) ^ (brow&7)))*16;
                ldsm4(bh_[np], baddr);
            }
            #pragma unroll
            for (int np = 0; np < 2; np++) {
                mma16816h(acc[2*np],   a_h, bh_[np]);
                mma16816h(acc[2*np+1], a_h, bh_[np]+2);
            }
        }
        __syncthreads();
    }

    #pragma unroll
    for (int nt = 0; nt < 4; nt++) {
        int n = n0 + ncol0 + nt*8 + 2*tig;
        float2 bb = *(const float2*)(bc + n);
        int ma = m0 + mrow0 + g;
        *(float2*)(out + (size_t)ma*128 + n) =
            make_float2(acc[nt][0] + bb.x, acc[nt][1] + bb.y);
        *(float2*)(out + (size_t)(ma+8)*128 + n) =
            make_float2(acc[nt][2] + bb.x, acc[nt][3] + bb.y);
    }
}

// ---------------------------------------------------------------------------
extern "C" void kernel_launch(void* const* d_in, const int* in_sizes, int n_in,
                              void* d_out, int out_size)
{
    const float* q    = (const float*)d_in[0];
    const float* k    = (const float*)d_in[1];
    const float* v    = (const float*)d_in[2];
    const float* mask = (const float*)d_in[3];
    const float* Wq   = (const float*)d_in[4];
    const float* Wk   = (const float*)d_in[5];
    const float* Wv   = (const float*)d_in[6];
    const float* Wc   = (const float*)d_in[7];
    const float* bc   = (const float*)d_in[8];
    float* out = (float*)d_out;

    const int qkv_smem  = 65536;
    const int attn_smem = 102400;
    const int outp_smem = 65536;

    cudaFuncSetAttribute(qkv_proj_kernel, cudaFuncAttributeMaxDynamicSharedMemorySize, qkv_smem);
    cudaFuncSetAttribute(attn_kernel, cudaFuncAttributeMaxDynamicSharedMemorySize, attn_smem);
    cudaFuncSetAttribute(out_proj_kernel, cudaFuncAttributeMaxDynamicSharedMemorySize, outp_smem);

    convert_kernel<<<dim3(96, 7), 256>>>(q, k, v, Wq, Wk, Wv, Wc);
    qkv_proj_kernel<<<dim3(8, 64, 3), 256, qkv_smem>>>();
    attn_kernel<<<dim3(8, 64), 256, attn_smem>>>(mask);
    out_proj_kernel<<<dim3(128, 2), 256, outp_smem>>>(bc, out);
}